// round 14
// baseline (speedup 1.0000x reference)
#include <cuda_runtime.h>
#include <cstdint>

// Causal unbiased-EMA instance norm, x: [B=8, C=256, T=16384] fp32 — EXACT
// via per-lane affine prefix scan, warp-autonomous dataflow.
//
//   s1 = a*s1 + (1-a)*x ; s2 = a*s2 + (1-a)*x^2 ; w = a*w + (1-a)  (= 1-a^t)
//   y  = (w*x - s1) * rsqrt(w*s2 + eps*w^2 - s1^2)   [floored at 1e-10]
//
// R14 = R12 (champion) at finer warp granularity: TPB=512, KP=32. Each warp
// owns a 1024-float segment end-to-end (own cp.async loads, pass 1, pass 2,
// coalesced store) with only syncwarp; the cross-warp affine prefix is a
// flag-chained smem relay (16 hops). Only __syncthreads is the flag reset at
// entry (graph replays leave stale smem). Math: constant-weight pass-1 dot
// product; w-saturation split (w == 1.0f exactly for t0 >= 1792, and
// ema_step_w == ema_step_1 at w == 1, so the split at warp 2 is exact).

#define T_LEN  16384
#define TPB    512
#define KP     (T_LEN / TPB)     // 32 steps per thread
#define NWARP  (TPB / 32)        // 16
#define WSEG   (T_LEN / NWARP)   // 1024 floats per warp

#define ALPHA_F 0.99f
#define OMA_F   0.01f
#define EPS_F   1e-5f
#define A32_F   0.72498034f      // 0.99^32

#define PAD(i)  ((i) + (((i) >> 5) << 2))      // +4 floats (16B) per 32-row
#define SMEM_F  (T_LEN + ((T_LEN >> 5) << 2))  // 18432 floats = 73728 B

__device__ __forceinline__ void cp_async16(float* smem_dst, const float* gmem_src) {
    uint32_t s = (uint32_t)__cvta_generic_to_shared(smem_dst);
    asm volatile("cp.async.cg.shared.global [%0], [%1], 16;" :: "r"(s), "l"(gmem_src));
}

__host__ __device__ constexpr float apow(int n) {
    float r = 1.0f;
    for (int i = 0; i < n; i++) r *= ALPHA_F;
    return r;
}

// pass-1 dot product, fully unrolled with constant weights; two accumulator
// pairs for ILP.  c_i = 0.01 * a^(KP-1-i).
template<int I>
__device__ __forceinline__ void warm_unroll(const float4* row,
                                            float& a0, float& b0,
                                            float& a1, float& b1) {
    if constexpr (I < KP / 4) {
        float4 v = row[I];
        constexpr float c0 = OMA_F * apow(KP - 1 - (4 * I + 0));
        constexpr float c1 = OMA_F * apow(KP - 1 - (4 * I + 1));
        constexpr float c2 = OMA_F * apow(KP - 1 - (4 * I + 2));
        constexpr float c3 = OMA_F * apow(KP - 1 - (4 * I + 3));
        float t0 = c0 * v.x;  a0 += t0;  b0 = fmaf(t0, v.x, b0);
        float t1 = c1 * v.y;  a1 += t1;  b1 = fmaf(t1, v.y, b1);
        float t2 = c2 * v.z;  a0 += t2;  b0 = fmaf(t2, v.z, b0);
        float t3 = c3 * v.w;  a1 += t3;  b1 = fmaf(t3, v.w, b1);
        warm_unroll<I + 1>(row, a0, b0, a1, b1);
    }
}

// full step: w still evolving (warps 0-1; exact also once w saturates)
__device__ __forceinline__ float ema_step_w(float xi, float& s1, float& s2, float& w) {
    float t = OMA_F * xi;
    s1 = fmaf(ALPHA_F, s1, t);
    s2 = fmaf(ALPHA_F, s2, t * xi);
    w  = fmaf(ALPHA_F, w, OMA_F);
    float num = fmaf(w, xi, -s1);
    float e   = fmaf(EPS_F, w, s2);
    float d   = fmaf(w, e, -(s1 * s1));
    d = fmaxf(d, 1e-10f);
    float r;
    asm("rsqrt.approx.f32 %0, %1;" : "=f"(r) : "f"(d));
    return num * r;
}

// saturated step: w == 1.0f exactly (t0 >= 1792; warp-uniform from warp 2)
__device__ __forceinline__ float ema_step_1(float xi, float& s1, float& s2) {
    float t = OMA_F * xi;
    s1 = fmaf(ALPHA_F, s1, t);
    s2 = fmaf(ALPHA_F, s2, t * xi);
    float num = xi - s1;
    float e   = s2 + EPS_F;
    float d   = fmaf(-s1, s1, e);
    d = fmaxf(d, 1e-10f);
    float r;
    asm("rsqrt.approx.f32 %0, %1;" : "=f"(r) : "f"(d));
    return num * r;
}

extern __shared__ float s_buf[];

__global__ void __launch_bounds__(TPB)
ema_norm_kernel(const float* __restrict__ x, float* __restrict__ y)
{
    __shared__ volatile float pub1[NWARP], pub2[NWARP], pubm[NWARP];
    __shared__ volatile int   flag[NWARP];

    const int tid  = threadIdx.x;
    const int lane = tid & 31;
    const int wid  = tid >> 5;
    const size_t base = (size_t)blockIdx.x * T_LEN;

    // flags must be reset every launch (graph replays reuse stale smem)
    if (tid < NWARP) flag[tid] = 0;
    __syncthreads();                  // only block-wide barrier in the kernel

    // ---- warp-local async load of this warp's 1024-float segment ----
    const int wbase = wid * WSEG;
    #pragma unroll
    for (int k = 0; k < WSEG / (32 * 4); k++) {      // 8 iters
        int i4 = wbase + k * (32 * 4) + 4 * lane;    // 16B aligned
        cp_async16(s_buf + PAD(i4), x + base + i4);
    }
    asm volatile("cp.async.commit_group;");
    asm volatile("cp.async.wait_group 0;" ::: "memory");
    __syncwarp();                     // warp's own region fully visible

    // ---- pass 1: constant-weight segment sums (this warp's rows only) ----
    const int t0 = tid * KP;
    const float4* row = reinterpret_cast<const float4*>(s_buf + PAD(t0));
    float a0 = 0.f, b0 = 0.f, a1 = 0.f, b1 = 0.f;
    warm_unroll<0>(row, a0, b0, a1, b1);
    float L1 = a0 + a1;
    float L2 = b0 + b1;

    // ---- in-warp affine inclusive scan: combine = vR + mR*vL ----
    float v1 = L1, v2 = L2, m = A32_F;
    #pragma unroll
    for (int d = 1; d < 32; d <<= 1) {
        float pv1 = __shfl_up_sync(0xffffffffu, v1, d);
        float pv2 = __shfl_up_sync(0xffffffffu, v2, d);
        float pm  = __shfl_up_sync(0xffffffffu, m,  d);
        if (lane >= d) {
            v1 = fmaf(m, pv1, v1);
            v2 = fmaf(m, pv2, v2);
            m *= pm;
        }
    }
    float ev1 = __shfl_up_sync(0xffffffffu, v1, 1);
    float ev2 = __shfl_up_sync(0xffffffffu, v2, 1);
    float em  = __shfl_up_sync(0xffffffffu, m,  1);
    if (lane == 0) { ev1 = 0.f; ev2 = 0.f; em = 1.f; }

    // ---- cross-warp prefix: flag-chained relay through smem ----
    float p1 = 0.f, p2 = 0.f, pm = 1.f;
    if (wid > 0) {
        if (lane == 0) { while (flag[wid - 1] == 0) {} }
        __syncwarp();
        __threadfence_block();
        p1 = pub1[wid - 1]; p2 = pub2[wid - 1]; pm = pubm[wid - 1];
    }
    if (wid < NWARP - 1 && lane == 31) {
        // this warp's inclusive prefix = own total (v,m at lane31) ∘ prefix
        pub1[wid] = fmaf(m, p1, v1);
        pub2[wid] = fmaf(m, p2, v2);
        pubm[wid] = m * pm;
        __threadfence_block();
        flag[wid] = 1;
    }

    // thread's exact start state
    float s1 = fmaf(em, p1, ev1);
    float s2 = fmaf(em, p2, ev2);
    float w  = 1.0f - pm * em;        // == 1.0f exactly for t0 >= 1792

    // ---- pass 2: normalize 32 steps from exact state, in-place ----
    float4* rw = reinterpret_cast<float4*>(s_buf + PAD(t0));
    if (wid >= 2) {                   // t0 >= 2048 -> w saturated (warp-uniform)
        #pragma unroll
        for (int i = 0; i < KP / 4; i++) {
            float4 v = rw[i];
            float4 o;
            o.x = ema_step_1(v.x, s1, s2);
            o.y = ema_step_1(v.y, s1, s2);
            o.z = ema_step_1(v.z, s1, s2);
            o.w = ema_step_1(v.w, s1, s2);
            rw[i] = o;
        }
    } else {
        #pragma unroll
        for (int i = 0; i < KP / 4; i++) {
            float4 v = rw[i];
            float4 o;
            o.x = ema_step_w(v.x, s1, s2, w);
            o.y = ema_step_w(v.y, s1, s2, w);
            o.z = ema_step_w(v.z, s1, s2, w);
            o.w = ema_step_w(v.w, s1, s2, w);
            rw[i] = o;
        }
    }
    __syncwarp();                     // warp's region fully written

    // ---- warp-local coalesced store (streaming hint; y never re-read) ----
    #pragma unroll
    for (int k = 0; k < WSEG / (32 * 4); k++) {
        int i4 = wbase + k * (32 * 4) + 4 * lane;
        float4 v = *reinterpret_cast<const float4*>(s_buf + PAD(i4));
        __stcs(reinterpret_cast<float4*>(y + base + i4), v);
    }
}

extern "C" void kernel_launch(void* const* d_in, const int* in_sizes, int n_in,
                              void* d_out, int out_size) {
    const float* x = (const float*)d_in[0];
    float*       y = (float*)d_out;

    int total = in_sizes[0];            // B*C*T
    int lanes = total / T_LEN;          // 2048 blocks, one per lane

    cudaFuncSetAttribute(ema_norm_kernel,
                         cudaFuncAttributeMaxDynamicSharedMemorySize,
                         SMEM_F * sizeof(float));
    ema_norm_kernel<<<lanes, TPB, SMEM_F * sizeof(float)>>>(x, y);
}

// round 15
// speedup vs baseline: 1.1994x; 1.1994x over previous
#include <cuda_runtime.h>
#include <cstdint>

// Causal unbiased-EMA instance norm, x: [B=8, C=256, T=16384] fp32 — EXACT
// via per-lane affine prefix scan, warp-autonomous dataflow (R12 champion).
//
//   s1 = a*s1 + (1-a)*x ; s2 = a*s2 + (1-a)*x^2 ; w = a*w + (1-a)  (= 1-a^t)
//   y  = (w*x - s1) * rsqrt(w*s2 + eps*w^2 - s1^2)   [floored at 1e-10]
//
// R15 = R12 + (a) two cp.async commit groups per warp: pass-1 partial sums of
// each thread's first 32 elements overlap the in-flight second 4KB; L is the
// affine composition L_hi ∘ L_lo. (b) streaming stores (st.global.cs).
// Everything else identical to R12: 8 warps own 2048-float segments
// end-to-end, cross-warp affine prefix via flag-chained smem relay, only
// __syncthreads is the flag reset at entry (graph replays leave stale smem).

#define T_LEN  16384
#define TPB    256
#define KP     (T_LEN / TPB)     // 64 steps per thread
#define NWARP  (TPB / 32)        // 8
#define WSEG   (T_LEN / NWARP)   // 2048 floats per warp

#define ALPHA_F 0.99f
#define OMA_F   0.01f
#define EPS_F   1e-5f
#define A32_F   0.72498034f      // 0.99^32
#define A64_F   0.52559649f      // 0.99^64
#define W1_TID  28               // tid >= 28 -> t0 >= 1792 -> w == 1.0f

#define PAD(i)  ((i) + (((i) >> 6) << 2))      // +4 floats (16B) per 64-row
#define SMEM_F  (T_LEN + ((T_LEN >> 6) << 2))  // 17408 floats = 69632 B

__device__ __forceinline__ void cp_async16(float* smem_dst, const float* gmem_src) {
    uint32_t s = (uint32_t)__cvta_generic_to_shared(smem_dst);
    asm volatile("cp.async.cg.shared.global [%0], [%1], 16;" :: "r"(s), "l"(gmem_src));
}

__host__ __device__ constexpr float apow(int n) {
    float r = 1.0f;
    for (int i = 0; i < n; i++) r *= ALPHA_F;
    return r;
}

// pass-1 dot product over elements [J0, J0+32) of the row, constant weights
// relative to a 32-length segment: c_j = 0.01 * a^(31 - (j - J0)).
template<int I, int J0>
__device__ __forceinline__ void warm_half(const float4* row,
                                          float& a0, float& b0,
                                          float& a1, float& b1) {
    if constexpr (I < 8) {
        float4 v = row[J0 / 4 + I];
        constexpr float c0 = OMA_F * apow(31 - (4 * I + 0));
        constexpr float c1 = OMA_F * apow(31 - (4 * I + 1));
        constexpr float c2 = OMA_F * apow(31 - (4 * I + 2));
        constexpr float c3 = OMA_F * apow(31 - (4 * I + 3));
        float t0 = c0 * v.x;  a0 += t0;  b0 = fmaf(t0, v.x, b0);
        float t1 = c1 * v.y;  a1 += t1;  b1 = fmaf(t1, v.y, b1);
        float t2 = c2 * v.z;  a0 += t2;  b0 = fmaf(t2, v.z, b0);
        float t3 = c3 * v.w;  a1 += t3;  b1 = fmaf(t3, v.w, b1);
        warm_half<I + 1, J0>(row, a0, b0, a1, b1);
    }
}

// full step: w still evolving (threads with t0 < 1792)
__device__ __forceinline__ float ema_step_w(float xi, float& s1, float& s2, float& w) {
    float t = OMA_F * xi;
    s1 = fmaf(ALPHA_F, s1, t);
    s2 = fmaf(ALPHA_F, s2, t * xi);
    w  = fmaf(ALPHA_F, w, OMA_F);
    float num = fmaf(w, xi, -s1);
    float e   = fmaf(EPS_F, w, s2);
    float d   = fmaf(w, e, -(s1 * s1));
    d = fmaxf(d, 1e-10f);
    float r;
    asm("rsqrt.approx.f32 %0, %1;" : "=f"(r) : "f"(d));
    return num * r;
}

// saturated step: w == 1.0f exactly (t0 >= 1792)
__device__ __forceinline__ float ema_step_1(float xi, float& s1, float& s2) {
    float t = OMA_F * xi;
    s1 = fmaf(ALPHA_F, s1, t);
    s2 = fmaf(ALPHA_F, s2, t * xi);
    float num = xi - s1;
    float e   = s2 + EPS_F;
    float d   = fmaf(-s1, s1, e);
    d = fmaxf(d, 1e-10f);
    float r;
    asm("rsqrt.approx.f32 %0, %1;" : "=f"(r) : "f"(d));
    return num * r;
}

extern __shared__ float s_buf[];

__global__ void __launch_bounds__(TPB)
ema_norm_kernel(const float* __restrict__ x, float* __restrict__ y)
{
    __shared__ volatile float pub1[NWARP], pub2[NWARP], pubm[NWARP];
    __shared__ volatile int   flag[NWARP];

    const int tid  = threadIdx.x;
    const int lane = tid & 31;
    const int wid  = tid >> 5;
    const size_t base = (size_t)blockIdx.x * T_LEN;

    // flags must be reset every launch (graph replays reuse stale smem)
    if (tid < NWARP) flag[tid] = 0;
    __syncthreads();                  // only block-wide barrier in the kernel

    // ---- warp-local async load, TWO commit groups ----
    // group A: elements [0,32) of each of this warp's 32 rows
    // group B: elements [32,64)
    const int wbase = wid * WSEG;
    #pragma unroll
    for (int r2 = 0; r2 < 8; r2++) {            // 8 LDGSTS: rows r2*4 .. r2*4+3 halves
        // lanes cover 4 rows x 8 float4 of the FIRST half of each row
        int rrow = r2 * 4 + (lane >> 3);        // row within warp segment
        int coff = (lane & 7) * 4;              // float offset in first half
        int i4 = wbase + rrow * KP + coff;
        cp_async16(s_buf + PAD(i4), x + base + i4);
    }
    asm volatile("cp.async.commit_group;");
    #pragma unroll
    for (int r2 = 0; r2 < 8; r2++) {
        int rrow = r2 * 4 + (lane >> 3);
        int coff = 32 + (lane & 7) * 4;         // second half
        int i4 = wbase + rrow * KP + coff;
        cp_async16(s_buf + PAD(i4), x + base + i4);
    }
    asm volatile("cp.async.commit_group;");

    // ---- pass 1a on first halves while second group is in flight ----
    asm volatile("cp.async.wait_group 1;" ::: "memory");
    __syncwarp();
    const int t0 = tid * KP;
    const float4* row = reinterpret_cast<const float4*>(s_buf + PAD(t0));
    float la0 = 0.f, lb0 = 0.f, la1 = 0.f, lb1 = 0.f;
    warm_half<0, 0>(row, la0, lb0, la1, lb1);
    float Llo1 = la0 + la1, Llo2 = lb0 + lb1;

    // ---- pass 1b on second halves ----
    asm volatile("cp.async.wait_group 0;" ::: "memory");
    __syncwarp();
    float ha0 = 0.f, hb0 = 0.f, ha1 = 0.f, hb1 = 0.f;
    warm_half<0, 32>(row, ha0, hb0, ha1, hb1);
    float Lhi1 = ha0 + ha1, Lhi2 = hb0 + hb1;

    // affine composition over the full 64-step segment: L = Lhi + a^32 * Llo
    float L1 = fmaf(A32_F, Llo1, Lhi1);
    float L2 = fmaf(A32_F, Llo2, Lhi2);

    // ---- in-warp affine inclusive scan: combine = vR + mR*vL ----
    float v1 = L1, v2 = L2, m = A64_F;
    #pragma unroll
    for (int d = 1; d < 32; d <<= 1) {
        float pv1 = __shfl_up_sync(0xffffffffu, v1, d);
        float pv2 = __shfl_up_sync(0xffffffffu, v2, d);
        float pm  = __shfl_up_sync(0xffffffffu, m,  d);
        if (lane >= d) {
            v1 = fmaf(m, pv1, v1);
            v2 = fmaf(m, pv2, v2);
            m *= pm;
        }
    }
    float ev1 = __shfl_up_sync(0xffffffffu, v1, 1);
    float ev2 = __shfl_up_sync(0xffffffffu, v2, 1);
    float em  = __shfl_up_sync(0xffffffffu, m,  1);
    if (lane == 0) { ev1 = 0.f; ev2 = 0.f; em = 1.f; }

    // ---- cross-warp prefix: flag-chained relay through smem ----
    float p1 = 0.f, p2 = 0.f, pm = 1.f;
    if (wid > 0) {
        if (lane == 0) { while (flag[wid - 1] == 0) {} }
        __syncwarp();
        __threadfence_block();
        p1 = pub1[wid - 1]; p2 = pub2[wid - 1]; pm = pubm[wid - 1];
    }
    if (wid < NWARP - 1 && lane == 31) {
        pub1[wid] = fmaf(m, p1, v1);
        pub2[wid] = fmaf(m, p2, v2);
        pubm[wid] = m * pm;
        __threadfence_block();
        flag[wid] = 1;
    }

    // thread's exact start state
    float s1 = fmaf(em, p1, ev1);
    float s2 = fmaf(em, p2, ev2);
    float w  = 1.0f - pm * em;        // == 1.0f exactly for tid >= 28

    // ---- pass 2: normalize 64 steps from exact state, in-place ----
    float4* rw = reinterpret_cast<float4*>(s_buf + PAD(t0));
    if (tid >= W1_TID) {
        #pragma unroll
        for (int i = 0; i < KP / 4; i++) {
            float4 v = rw[i];
            float4 o;
            o.x = ema_step_1(v.x, s1, s2);
            o.y = ema_step_1(v.y, s1, s2);
            o.z = ema_step_1(v.z, s1, s2);
            o.w = ema_step_1(v.w, s1, s2);
            rw[i] = o;
        }
    } else {
        #pragma unroll
        for (int i = 0; i < KP / 4; i++) {
            float4 v = rw[i];
            float4 o;
            o.x = ema_step_w(v.x, s1, s2, w);
            o.y = ema_step_w(v.y, s1, s2, w);
            o.z = ema_step_w(v.z, s1, s2, w);
            o.w = ema_step_w(v.w, s1, s2, w);
            rw[i] = o;
        }
    }
    __syncwarp();                     // warp's region fully written

    // ---- warp-local coalesced store (streaming: y never re-read) ----
    #pragma unroll
    for (int k = 0; k < WSEG / (32 * 4); k++) {
        int i4 = wbase + k * (32 * 4) + 4 * lane;
        float4 v = *reinterpret_cast<const float4*>(s_buf + PAD(i4));
        __stcs(reinterpret_cast<float4*>(y + base + i4), v);
    }
}

extern "C" void kernel_launch(void* const* d_in, const int* in_sizes, int n_in,
                              void* d_out, int out_size) {
    const float* x = (const float*)d_in[0];
    float*       y = (float*)d_out;

    int total = in_sizes[0];            // B*C*T
    int lanes = total / T_LEN;          // 2048 blocks, one per lane

    cudaFuncSetAttribute(ema_norm_kernel,
                         cudaFuncAttributeMaxDynamicSharedMemorySize,
                         SMEM_F * sizeof(float));
    ema_norm_kernel<<<lanes, TPB, SMEM_F * sizeof(float)>>>(x, y);
}

// round 16
// speedup vs baseline: 1.2502x; 1.0424x over previous
#include <cuda_runtime.h>
#include <cstdint>

// Causal unbiased-EMA instance norm, x: [B=8, C=256, T=16384] fp32 — EXACT
// via per-lane affine prefix scan, warp-autonomous dataflow.
//
//   s1 = a*s1 + (1-a)*x ; s2 = a*s2 + (1-a)*x^2 ; w = a*w + (1-a)  (= 1-a^t)
//   y  = (w*x - s1) * rsqrt(max(w*s2 - s1^2, 0) + eps*w^2)
//
// R16 = R12 champion bit-identical + ONE change: streaming stores
// (st.global.cs) — output is never re-read, early-evict keeps L2 for input.
//
// Structure: 8 warps per block, each owns a 2048-float segment end-to-end
// (own cp.async loads in one ascending sweep, pass 1, pass 2, coalesced
// store) with only syncwarp. Cross-warp affine prefix is a flag-chained smem
// relay. The only __syncthreads is the flag reset at entry (graph replays
// leave stale smem).

#define T_LEN  16384
#define TPB    256
#define KP     (T_LEN / TPB)     // 64 steps per thread
#define NWARP  (TPB / 32)        // 8
#define WSEG   (T_LEN / NWARP)   // 2048 floats per warp

#define ALPHA_F 0.99f
#define OMA_F   0.01f
#define EPS_F   1e-5f
#define A64_F   0.52559649f      // 0.99^64
#define W1_TID  28               // tid >= 28 -> t0 >= 1792 -> w == 1.0f

#define PAD(i)  ((i) + (((i) >> 6) << 2))      // +4 floats (16B) per 64-row
#define SMEM_F  (T_LEN + ((T_LEN >> 6) << 2))  // 17408 floats = 69632 B

__device__ __forceinline__ void cp_async16(float* smem_dst, const float* gmem_src) {
    uint32_t s = (uint32_t)__cvta_generic_to_shared(smem_dst);
    asm volatile("cp.async.cg.shared.global [%0], [%1], 16;" :: "r"(s), "l"(gmem_src));
}

__host__ __device__ constexpr float apow(int n) {
    float r = 1.0f;
    for (int i = 0; i < n; i++) r *= ALPHA_F;
    return r;
}

// pass-1 dot product, fully unrolled with constant weights; two accumulator
// pairs for ILP.  c_i = 0.01 * a^(KP-1-i).
template<int I>
__device__ __forceinline__ void warm_unroll(const float4* row,
                                            float& a0, float& b0,
                                            float& a1, float& b1) {
    if constexpr (I < KP / 4) {
        float4 v = row[I];
        constexpr float c0 = OMA_F * apow(KP - 1 - (4 * I + 0));
        constexpr float c1 = OMA_F * apow(KP - 1 - (4 * I + 1));
        constexpr float c2 = OMA_F * apow(KP - 1 - (4 * I + 2));
        constexpr float c3 = OMA_F * apow(KP - 1 - (4 * I + 3));
        float t0 = c0 * v.x;  a0 += t0;  b0 = fmaf(t0, v.x, b0);
        float t1 = c1 * v.y;  a1 += t1;  b1 = fmaf(t1, v.y, b1);
        float t2 = c2 * v.z;  a0 += t2;  b0 = fmaf(t2, v.z, b0);
        float t3 = c3 * v.w;  a1 += t3;  b1 = fmaf(t3, v.w, b1);
        warm_unroll<I + 1>(row, a0, b0, a1, b1);
    }
}

// full step: w still evolving (threads with t0 < 1792)
__device__ __forceinline__ float ema_step_w(float xi, float& s1, float& s2, float& w) {
    float t = OMA_F * xi;
    s1 = fmaf(ALPHA_F, s1, t);
    s2 = fmaf(ALPHA_F, s2, t * xi);
    w  = fmaf(ALPHA_F, w, OMA_F);
    float num = fmaf(w, xi, -s1);
    float e   = fmaf(EPS_F, w, s2);
    float d   = fmaf(w, e, -(s1 * s1));
    d = fmaxf(d, 1e-10f);
    float r;
    asm("rsqrt.approx.f32 %0, %1;" : "=f"(r) : "f"(d));
    return num * r;
}

// saturated step: w == 1.0f exactly (t0 >= 1792)
__device__ __forceinline__ float ema_step_1(float xi, float& s1, float& s2) {
    float t = OMA_F * xi;
    s1 = fmaf(ALPHA_F, s1, t);
    s2 = fmaf(ALPHA_F, s2, t * xi);
    float num = xi - s1;
    float e   = s2 + EPS_F;
    float d   = fmaf(-s1, s1, e);
    d = fmaxf(d, 1e-10f);
    float r;
    asm("rsqrt.approx.f32 %0, %1;" : "=f"(r) : "f"(d));
    return num * r;
}

extern __shared__ float s_buf[];

__global__ void __launch_bounds__(TPB)
ema_norm_kernel(const float* __restrict__ x, float* __restrict__ y)
{
    __shared__ volatile float pub1[NWARP], pub2[NWARP], pubm[NWARP];
    __shared__ volatile int   flag[NWARP];

    const int tid  = threadIdx.x;
    const int lane = tid & 31;
    const int wid  = tid >> 5;
    const size_t base = (size_t)blockIdx.x * T_LEN;

    // flags must be reset every launch (graph replays reuse stale smem)
    if (tid < NWARP) flag[tid] = 0;
    __syncthreads();                  // only block-wide barrier in the kernel

    // ---- warp-local async load: one ascending coalesced sweep ----
    const int wbase = wid * WSEG;
    #pragma unroll
    for (int k = 0; k < WSEG / (32 * 4); k++) {      // 16 iters
        int i4 = wbase + k * (32 * 4) + 4 * lane;    // 16B aligned
        cp_async16(s_buf + PAD(i4), x + base + i4);
    }
    asm volatile("cp.async.commit_group;");
    asm volatile("cp.async.wait_group 0;" ::: "memory");
    __syncwarp();                     // warp's own region fully visible

    // ---- pass 1: constant-weight segment sums (this warp's rows only) ----
    const int t0 = tid * KP;
    const float4* row = reinterpret_cast<const float4*>(s_buf + PAD(t0));
    float a0 = 0.f, b0 = 0.f, a1 = 0.f, b1 = 0.f;
    warm_unroll<0>(row, a0, b0, a1, b1);
    float L1 = a0 + a1;
    float L2 = b0 + b1;

    // ---- in-warp affine inclusive scan: combine = vR + mR*vL ----
    float v1 = L1, v2 = L2, m = A64_F;
    #pragma unroll
    for (int d = 1; d < 32; d <<= 1) {
        float pv1 = __shfl_up_sync(0xffffffffu, v1, d);
        float pv2 = __shfl_up_sync(0xffffffffu, v2, d);
        float pm  = __shfl_up_sync(0xffffffffu, m,  d);
        if (lane >= d) {
            v1 = fmaf(m, pv1, v1);
            v2 = fmaf(m, pv2, v2);
            m *= pm;
        }
    }
    float ev1 = __shfl_up_sync(0xffffffffu, v1, 1);
    float ev2 = __shfl_up_sync(0xffffffffu, v2, 1);
    float em  = __shfl_up_sync(0xffffffffu, m,  1);
    if (lane == 0) { ev1 = 0.f; ev2 = 0.f; em = 1.f; }

    // ---- cross-warp prefix: flag-chained relay through smem ----
    float p1 = 0.f, p2 = 0.f, pm = 1.f;
    if (wid > 0) {
        if (lane == 0) { while (flag[wid - 1] == 0) {} }
        __syncwarp();
        __threadfence_block();
        p1 = pub1[wid - 1]; p2 = pub2[wid - 1]; pm = pubm[wid - 1];
    }
    if (wid < NWARP - 1 && lane == 31) {
        // this warp's inclusive prefix = own total (v,m at lane31) ∘ prefix
        pub1[wid] = fmaf(m, p1, v1);
        pub2[wid] = fmaf(m, p2, v2);
        pubm[wid] = m * pm;
        __threadfence_block();
        flag[wid] = 1;
    }

    // thread's exact start state
    float s1 = fmaf(em, p1, ev1);
    float s2 = fmaf(em, p2, ev2);
    float w  = 1.0f - pm * em;        // == 1.0f exactly for tid >= 28

    // ---- pass 2: normalize 64 steps from exact state, in-place ----
    float4* rw = reinterpret_cast<float4*>(s_buf + PAD(t0));
    if (tid >= W1_TID) {
        #pragma unroll
        for (int i = 0; i < KP / 4; i++) {
            float4 v = rw[i];
            float4 o;
            o.x = ema_step_1(v.x, s1, s2);
            o.y = ema_step_1(v.y, s1, s2);
            o.z = ema_step_1(v.z, s1, s2);
            o.w = ema_step_1(v.w, s1, s2);
            rw[i] = o;
        }
    } else {
        #pragma unroll
        for (int i = 0; i < KP / 4; i++) {
            float4 v = rw[i];
            float4 o;
            o.x = ema_step_w(v.x, s1, s2, w);
            o.y = ema_step_w(v.y, s1, s2, w);
            o.z = ema_step_w(v.z, s1, s2, w);
            o.w = ema_step_w(v.w, s1, s2, w);
            rw[i] = o;
        }
    }
    __syncwarp();                     // warp's region fully written

    // ---- warp-local coalesced store (streaming: y never re-read) ----
    #pragma unroll
    for (int k = 0; k < WSEG / (32 * 4); k++) {
        int i4 = wbase + k * (32 * 4) + 4 * lane;
        float4 v = *reinterpret_cast<const float4*>(s_buf + PAD(i4));
        __stcs(reinterpret_cast<float4*>(y + base + i4), v);
    }
}

extern "C" void kernel_launch(void* const* d_in, const int* in_sizes, int n_in,
                              void* d_out, int out_size) {
    const float* x = (const float*)d_in[0];
    float*       y = (float*)d_out;

    int total = in_sizes[0];            // B*C*T
    int lanes = total / T_LEN;          // 2048 blocks, one per lane

    cudaFuncSetAttribute(ema_norm_kernel,
                         cudaFuncAttributeMaxDynamicSharedMemorySize,
                         SMEM_F * sizeof(float));
    ema_norm_kernel<<<lanes, TPB, SMEM_F * sizeof(float)>>>(x, y);
}